// round 5
// baseline (speedup 1.0000x reference)
#include <cuda_runtime.h>
#include <math.h>

#define BQ 128
#define TQ 1024
#define IQ 128
#define HQ 512
#define G4 2048
#define BT (BQ*TQ)
#define MAXLEV 16

// Static scratch (allocation-free rule: __device__ globals)
static __device__ float g_pre[(size_t)BT * G4];     // pre-gates at m==1 positions (~10% touched)
static __device__ float g_H[(size_t)BT * HQ];       // carry h_t where m_{t+1}==1
static __device__ float g_C[(size_t)BT * HQ];       // carry c_t where m_{t+1}==1
static __device__ int   g_emit[BT];                 // output slot for emb[b,t] or -1
static __device__ unsigned char g_m[BT];            // boundary mask
static __device__ int   g_lvlcount[MAXLEV + 1];
static __device__ int   g_lvllist[(size_t)(MAXLEV + 1) * BT];
static __device__ int   g_workcount;
static __device__ int   g_work[BT];                 // positions needing any compute

__device__ __forceinline__ float sigf(float v) { return 1.0f / (1.0f + expf(-v)); }

__global__ void k_init() {
  int i = blockIdx.x * blockDim.x + threadIdx.x;
  if (i < BT) g_emit[i] = -1;
  if (i <= MAXLEV) g_lvlcount[i] = 0;
  if (i == 0) g_workcount = 0;
}

// Per-row: warp cooperatively stages the boundary mask into shared memory
// (coalesced), then thread 0 runs the serial bookkeeping against shared.
__global__ void k_row(const int* __restrict__ mask, const int* __restrict__ length,
                      float* __restrict__ out, int K, int has_wn) {
  __shared__ unsigned char ml[TQ];
  int b = blockIdx.x;
  int len = length[b];
  for (int t = threadIdx.x; t < TQ; t += 32) {
    int mv = (mask[b*TQ + t] != 0) ? 1 : 0;
    if (t == 0) mv = 0;
    if (t == len - 1) mv = 1;
    ml[t] = (unsigned char)mv;
    g_m[b*TQ + t] = (unsigned char)mv;
  }
  __syncthreads();
  if (threadIdx.x != 0) return;

  int wn = 0, lvl = 0;
  for (int t = 0; t < TQ; t++) {
    if (ml[t]) {
      wn++;
      lvl++;
      int L = lvl < MAXLEV ? lvl : MAXLEV;
      int idx = atomicAdd(&g_lvlcount[L], 1);
      g_lvllist[(size_t)L * BT + idx] = b*TQ + t;
    } else lvl = 0;
  }
  // padded: rightmost (K - wn) zeros become ones
  int need = K - wn;
  int cut = TQ;
  if (need > 0) {
    int cnt = 0;
    for (int t = TQ - 1; t >= 0; t--) {
      if (!ml[t]) { cnt++; if (cnt == need) { cut = t; break; } }
    }
  }
  int k = 0;
  for (int t = 0; t < TQ && k < K; t++) {
    if (ml[t] || t >= cut) {
      int flat = b*TQ + t - 1;               // (b*T + col - 1) mod (B*T)
      if (flat < 0) flat += BT;
      g_emit[flat] = b*K + k;
      k++;
    }
  }
  if (has_wn) out[(size_t)BQ * (size_t)K * HQ + b] = (float)wn;
}

// Build worklist of positions that need ANY computation:
// m_t==1 (store pre), m_{t+1}==1 (store carry), or emit slot (output)
__global__ void k_work() {
  int p = blockIdx.x * blockDim.x + threadIdx.x;
  if (p >= BT) return;
  bool need = g_m[p] || ((p + 1 < BT) && g_m[p + 1]) || (g_emit[p] >= 0);
  if (need) {
    int idx = atomicAdd(&g_workcount, 1);
    g_work[idx] = p;
  }
}

#define BM 64
#define BN 128
#define BK 32

// Phase 1: gates_x = x @ W_ih^T + b  over worklist positions.
// m==0 positions: full epilogue (c_in = h_in = 0). m==1 positions: store pre.
__global__ __launch_bounds__(128) void k_main(
    const float* __restrict__ x, const int* __restrict__ length,
    const float* __restrict__ W_ih, const float* __restrict__ b_ih,
    const float* __restrict__ b_hh, float* __restrict__ out) {
  __shared__ float Xs[BK][BM + 4];
  __shared__ float Ws[BK][BN + 4];
  __shared__ int plist[BM];
  int count = g_workcount;
  int nmt = (count + BM - 1) / BM;
  int hbase = blockIdx.y * 32;
  int tid = threadIdx.x;
  int tx = tid & 15;   // 16 groups of 8 cols
  int ty = tid >> 4;   // 8 groups of 8 rows

  float bias[8];
  #pragma unroll
  for (int ni = 0; ni < 8; ni++) {
    int c = tx*8 + ni;
    int j = (c & 3)*HQ + hbase + (c >> 2);
    bias[ni] = __ldg(&b_ih[j]) + __ldg(&b_hh[j]);
  }

  for (int mt = blockIdx.x; mt < nmt; mt += gridDim.x) {
    __syncthreads();
    if (tid < BM) {
      int idx = mt*BM + tid;
      plist[tid] = (idx < count) ? g_work[idx] : -1;
    }
    __syncthreads();

    float acc[8][8];
    #pragma unroll
    for (int i = 0; i < 8; i++)
      #pragma unroll
      for (int j = 0; j < 8; j++) acc[i][j] = 0.0f;

    #pragma unroll
    for (int kc = 0; kc < IQ; kc += BK) {
      #pragma unroll
      for (int i = 0; i < 4; i++) {
        int lin = tid + i*128;
        int row = lin >> 3, kk = lin & 7;
        int p = plist[row]; if (p < 0) p = 0;
        float4 v = *((const float4*)(x + (size_t)p*IQ + kc) + kk);
        Xs[kk*4+0][row] = v.x; Xs[kk*4+1][row] = v.y;
        Xs[kk*4+2][row] = v.z; Xs[kk*4+3][row] = v.w;
      }
      #pragma unroll
      for (int i = 0; i < 8; i++) {
        int lin = tid + i*128;
        int c = lin >> 3, kk = lin & 7;
        int j = (c & 3)*HQ + hbase + (c >> 2);
        float4 v = *((const float4*)(W_ih + (size_t)j*IQ + kc) + kk);
        Ws[kk*4+0][c] = v.x; Ws[kk*4+1][c] = v.y;
        Ws[kk*4+2][c] = v.z; Ws[kk*4+3][c] = v.w;
      }
      __syncthreads();
      #pragma unroll
      for (int k = 0; k < BK; k++) {
        float4 a0 = *((const float4*)&Xs[k][ty*8]);
        float4 a1 = *((const float4*)&Xs[k][ty*8+4]);
        float4 b0 = *((const float4*)&Ws[k][tx*8]);
        float4 b1 = *((const float4*)&Ws[k][tx*8+4]);
        float av[8] = {a0.x,a0.y,a0.z,a0.w,a1.x,a1.y,a1.z,a1.w};
        float bv[8] = {b0.x,b0.y,b0.z,b0.w,b1.x,b1.y,b1.z,b1.w};
        #pragma unroll
        for (int mi = 0; mi < 8; mi++)
          #pragma unroll
          for (int ni = 0; ni < 8; ni++)
            acc[mi][ni] += av[mi]*bv[ni];
      }
      __syncthreads();
    }

    #pragma unroll
    for (int mi = 0; mi < 8; mi++) {
      int p = plist[ty*8 + mi];
      if (p < 0) continue;
      int t = p & (TQ-1);
      int mt_flag = g_m[p];
      if (mt_flag) {
        #pragma unroll
        for (int ni = 0; ni < 8; ni++) {
          int c = tx*8 + ni;
          int j = (c & 3)*HQ + hbase + (c >> 2);
          g_pre[(size_t)p*G4 + j] = acc[mi][ni] + bias[ni];
        }
      } else {
        int len = __ldg(&length[p >> 10]);
        float a = (t < len) ? 1.0f : 0.0f;
        int sf = (p + 1 < BT) ? (int)g_m[p+1] : 0;
        int em = g_emit[p];
        if (!sf && em < 0) continue;
        #pragma unroll
        for (int u = 0; u < 2; u++) {
          int hu = hbase + tx*2 + u;
          float vi = acc[mi][u*4+0] + bias[u*4+0];
          float vg = acc[mi][u*4+2] + bias[u*4+2];
          float vo = acc[mi][u*4+3] + bias[u*4+3];
          float c2 = sigf(vi) * tanhf(vg);          // c_in = 0, f-gate irrelevant
          float h2 = sigf(vo) * tanhf(c2);
          float hv = a * h2;
          if (sf) {
            g_H[(size_t)p*HQ + hu] = hv;
            g_C[(size_t)p*HQ + hu] = a * c2;
          }
          if (em >= 0) out[(size_t)em*HQ + hu] = hv;
        }
      }
    }
  }
}

// Level pass L: gates = pre + h_{t-1} @ W_hh^T at positions of dependency depth L
__global__ __launch_bounds__(128) void k_level(
    const float* __restrict__ W_hh, const int* __restrict__ length,
    float* __restrict__ out, int L) {
  __shared__ float Hs[BK][BM + 4];
  __shared__ float Ws[BK][BN + 4];
  __shared__ int plist[BM];
  int count = g_lvlcount[L];
  if (count == 0) return;
  int nmt = (count + BM - 1) / BM;
  int hbase = blockIdx.y * 32;
  int tid = threadIdx.x;
  int tx = tid & 15;
  int ty = tid >> 4;

  for (int mt = blockIdx.x; mt < nmt; mt += gridDim.x) {
    __syncthreads();
    if (tid < BM) {
      int idx = mt*BM + tid;
      plist[tid] = (idx < count) ? g_lvllist[(size_t)L*BT + idx] : -1;
    }
    __syncthreads();

    float acc[8][8];
    #pragma unroll
    for (int i = 0; i < 8; i++)
      #pragma unroll
      for (int j = 0; j < 8; j++) acc[i][j] = 0.0f;

    for (int kc = 0; kc < HQ; kc += BK) {
      #pragma unroll
      for (int i = 0; i < 4; i++) {
        int lin = tid + i*128;
        int row = lin >> 3, kk = lin & 7;
        int p = plist[row]; if (p < 0) p = 1;     // p-1 >= 0 safe
        float4 v = *((const float4*)(g_H + (size_t)(p-1)*HQ + kc) + kk);
        Hs[kk*4+0][row] = v.x; Hs[kk*4+1][row] = v.y;
        Hs[kk*4+2][row] = v.z; Hs[kk*4+3][row] = v.w;
      }
      #pragma unroll
      for (int i = 0; i < 8; i++) {
        int lin = tid + i*128;
        int c = lin >> 3, kk = lin & 7;
        int j = (c & 3)*HQ + hbase + (c >> 2);
        float4 v = *((const float4*)(W_hh + (size_t)j*HQ + kc) + kk);
        Ws[kk*4+0][c] = v.x; Ws[kk*4+1][c] = v.y;
        Ws[kk*4+2][c] = v.z; Ws[kk*4+3][c] = v.w;
      }
      __syncthreads();
      #pragma unroll
      for (int k = 0; k < BK; k++) {
        float4 a0 = *((const float4*)&Hs[k][ty*8]);
        float4 a1 = *((const float4*)&Hs[k][ty*8+4]);
        float4 b0 = *((const float4*)&Ws[k][tx*8]);
        float4 b1 = *((const float4*)&Ws[k][tx*8+4]);
        float av[8] = {a0.x,a0.y,a0.z,a0.w,a1.x,a1.y,a1.z,a1.w};
        float bv[8] = {b0.x,b0.y,b0.z,b0.w,b1.x,b1.y,b1.z,b1.w};
        #pragma unroll
        for (int mi = 0; mi < 8; mi++)
          #pragma unroll
          for (int ni = 0; ni < 8; ni++)
            acc[mi][ni] += av[mi]*bv[ni];
      }
      __syncthreads();
    }

    #pragma unroll
    for (int mi = 0; mi < 8; mi++) {
      int p = plist[ty*8 + mi];
      if (p < 0) continue;
      int t = p & (TQ-1);
      int len = __ldg(&length[p >> 10]);
      float a = (t < len) ? 1.0f : 0.0f;
      int sf = (p + 1 < BT) ? (int)g_m[p+1] : 0;
      int em = g_emit[p];
      #pragma unroll
      for (int u = 0; u < 2; u++) {
        int hu = hbase + tx*2 + u;
        size_t pb = (size_t)p*G4 + hu;
        float vi = acc[mi][u*4+0] + g_pre[pb + 0*HQ];
        float vf = acc[mi][u*4+1] + g_pre[pb + 1*HQ];
        float vg = acc[mi][u*4+2] + g_pre[pb + 2*HQ];
        float vo = acc[mi][u*4+3] + g_pre[pb + 3*HQ];
        float hin = g_H[(size_t)(p-1)*HQ + hu];
        float cin = g_C[(size_t)(p-1)*HQ + hu];
        float c2 = sigf(vf)*cin + sigf(vi)*tanhf(vg);
        float h2 = sigf(vo)*tanhf(c2);
        float hv = a*h2 + (1.0f - a)*hin;
        float cv = a*c2 + (1.0f - a)*cin;
        if (sf) {
          g_H[(size_t)p*HQ + hu] = hv;
          g_C[(size_t)p*HQ + hu] = cv;
        }
        if (em >= 0) out[(size_t)em*HQ + hu] = a*h2;
      }
    }
  }
}

extern "C" void kernel_launch(void* const* d_in, const int* in_sizes, int n_in,
                              void* d_out, int out_size) {
  const float* x      = (const float*)d_in[0];
  const int*   mask   = (const int*)d_in[1];
  const int*   length = (const int*)d_in[2];
  const float* W_ih   = (const float*)d_in[3];
  const float* W_hh   = (const float*)d_in[4];
  const float* b_ih   = (const float*)d_in[5];
  const float* b_hh   = (const float*)d_in[6];
  float* out = (float*)d_out;

  long long per = (long long)BQ * HQ;
  int K, has_wn;
  if ((long long)out_size % per == 0) { K = (int)((long long)out_size / per); has_wn = 0; }
  else { K = (int)(((long long)out_size - BQ) / per); has_wn = 1; }

  k_init<<<(BT + 255)/256, 256>>>();
  k_row<<<BQ, 32>>>(mask, length, out, K, has_wn);
  k_work<<<(BT + 255)/256, 256>>>();
  k_main<<<dim3(512, 16), 128>>>(x, length, W_ih, b_ih, b_hh, out);
  for (int L = 1; L <= MAXLEV; L++) {
    int gx = (L == 1) ? 256 : (L == 2) ? 32 : 8;
    k_level<<<dim3(gx, 16), 128>>>(W_hh, length, out, L);
  }
}

// round 12
// speedup vs baseline: 1.9988x; 1.9988x over previous
#include <cuda_runtime.h>
#include <math.h>

#define BQ 128
#define TQ 1024
#define IQ 128
#define HQ 512
#define G4 2048
#define BT (BQ*TQ)
#define MAXLEV 16

#define BM 64
#define BN 128
#define BKC 32
#define AS_STR 36
#define BS_STR 132
#define ES_STR 132

// Static scratch (allocation-free rule: __device__ globals)
static __device__ float g_pre[(size_t)BT * G4];
static __device__ float g_H[(size_t)BT * HQ];
static __device__ float g_C[(size_t)BT * HQ];
static __device__ int   g_emit[BT];
static __device__ unsigned char g_m[BT];
static __device__ int   g_lvlcount[MAXLEV + 1];
static __device__ int   g_lvllist[(size_t)(MAXLEV + 1) * BT];
static __device__ int   g_workcount;
static __device__ int   g_work[BT];

__device__ __forceinline__ float sigf(float v) { return 1.0f / (1.0f + expf(-v)); }

__device__ __forceinline__ float tf32r(float f) {
  unsigned u; asm("cvt.rna.tf32.f32 %0, %1;" : "=r"(u) : "f"(f));
  return __uint_as_float(u);
}
__device__ __forceinline__ void mma8(float* c, const unsigned* a, const unsigned* b) {
  asm volatile(
    "mma.sync.aligned.m16n8k8.row.col.f32.tf32.tf32.f32 "
    "{%0,%1,%2,%3},{%4,%5,%6,%7},{%8,%9},{%0,%1,%2,%3};\n"
    : "+f"(c[0]), "+f"(c[1]), "+f"(c[2]), "+f"(c[3])
    : "r"(a[0]), "r"(a[1]), "r"(a[2]), "r"(a[3]), "r"(b[0]), "r"(b[1]));
}

__global__ void k_init() {
  int i = blockIdx.x * blockDim.x + threadIdx.x;
  if (i < BT) g_emit[i] = -1;
  if (i <= MAXLEV) g_lvlcount[i] = 0;
  if (i == 0) g_workcount = 0;
}

__global__ void k_row(const int* __restrict__ mask, const int* __restrict__ length,
                      float* __restrict__ out, int K, int has_wn) {
  __shared__ unsigned char ml[TQ];
  int b = blockIdx.x;
  int len = length[b];
  for (int t = threadIdx.x; t < TQ; t += 32) {
    int mv = (mask[b*TQ + t] != 0) ? 1 : 0;
    if (t == 0) mv = 0;
    if (t == len - 1) mv = 1;
    ml[t] = (unsigned char)mv;
    g_m[b*TQ + t] = (unsigned char)mv;
  }
  __syncthreads();
  if (threadIdx.x != 0) return;

  int wn = 0, lvl = 0;
  for (int t = 0; t < TQ; t++) {
    if (ml[t]) {
      wn++; lvl++;
      int L = lvl < MAXLEV ? lvl : MAXLEV;
      int idx = atomicAdd(&g_lvlcount[L], 1);
      g_lvllist[(size_t)L * BT + idx] = b*TQ + t;
    } else lvl = 0;
  }
  int need = K - wn;
  int cut = TQ;
  if (need > 0) {
    int cnt = 0;
    for (int t = TQ - 1; t >= 0; t--) {
      if (!ml[t]) { cnt++; if (cnt == need) { cut = t; break; } }
    }
  }
  int k = 0;
  for (int t = 0; t < TQ && k < K; t++) {
    if (ml[t] || t >= cut) {
      int flat = b*TQ + t - 1;
      if (flat < 0) flat += BT;
      g_emit[flat] = b*K + k;
      k++;
    }
  }
  if (has_wn) out[(size_t)BQ * (size_t)K * HQ + b] = (float)wn;
}

__global__ void k_work() {
  int p = blockIdx.x * blockDim.x + threadIdx.x;
  if (p >= BT) return;
  bool need = g_m[p] || ((p + 1 < BT) && g_m[p + 1]) || (g_emit[p] >= 0);
  if (need) {
    int idx = atomicAdd(&g_workcount, 1);
    g_work[idx] = p;
  }
}

// ---------- shared GEMM core ----------
// SMEM plan: SM[8448] floats. As = SM[0..2304) as [64][36];
// Bs = SM[2304..6528) as [32][132]; Es (post-mainloop) = SM as [64][132].

// Phase 1: gates_x = x @ W_ih^T + b over worklist positions (tf32 tensor MMA).
__global__ __launch_bounds__(256) void k_main(
    const float* __restrict__ x, const int* __restrict__ length,
    const float* __restrict__ W_ih, const float* __restrict__ b_ih,
    const float* __restrict__ b_hh, float* __restrict__ out) {
  __shared__ float SM[8448];
  __shared__ float Bb[BN];
  __shared__ int plist[BM];
  float* As = SM;            // [64][36]
  float* Bs = SM + 2304;     // [32][132]
  float* Es = SM;            // [64][132]

  int count = g_workcount;
  int nmt = (count + BM - 1) / BM;
  int hbase = blockIdx.y * 32;
  int tid = threadIdx.x;
  int wid = tid >> 5, lane = tid & 31;
  int wm = wid & 1, wn = wid >> 1;
  int g8 = lane >> 2, tg = lane & 3;

  if (tid < BN) {
    int c = tid;
    int j = (c & 3)*HQ + hbase + (c >> 2);
    Bb[c] = __ldg(&b_ih[j]) + __ldg(&b_hh[j]);
  }

  for (int mt = blockIdx.x; mt < nmt; mt += gridDim.x) {
    __syncthreads();
    if (tid < BM) {
      int idx = mt*BM + tid;
      plist[tid] = (idx < count) ? g_work[idx] : -1;
    }
    __syncthreads();

    float acc[2][4][4];
    #pragma unroll
    for (int i = 0; i < 2; i++)
      #pragma unroll
      for (int j = 0; j < 4; j++)
        #pragma unroll
        for (int q = 0; q < 4; q++) acc[i][j][q] = 0.0f;

    #pragma unroll
    for (int kc = 0; kc < IQ; kc += BKC) {
      // stage A: 64 rows x 32 k (tf32-rounded)
      {
        int row = tid >> 2, q = tid & 3;
        int p = plist[row]; if (p < 0) p = 0;
        const float* src = x + (size_t)p*IQ + kc + q*8;
        #pragma unroll
        for (int h = 0; h < 2; h++) {
          float4 v = *((const float4*)(src + h*4));
          float* d = As + row*AS_STR + q*8 + h*4;
          d[0]=tf32r(v.x); d[1]=tf32r(v.y); d[2]=tf32r(v.z); d[3]=tf32r(v.w);
        }
      }
      // stage B: 32 k x 128 cols
      {
        int c = tid >> 1, half = tid & 1;
        int j = (c & 3)*HQ + hbase + (c >> 2);
        const float* src = W_ih + (size_t)j*IQ + kc + half*16;
        #pragma unroll
        for (int h = 0; h < 4; h++) {
          float4 v = *((const float4*)(src + h*4));
          int kk = half*16 + h*4;
          Bs[(kk+0)*BS_STR + c] = tf32r(v.x);
          Bs[(kk+1)*BS_STR + c] = tf32r(v.y);
          Bs[(kk+2)*BS_STR + c] = tf32r(v.z);
          Bs[(kk+3)*BS_STR + c] = tf32r(v.w);
        }
      }
      __syncthreads();
      #pragma unroll
      for (int k8 = 0; k8 < 4; k8++) {
        int kb = k8*8;
        unsigned a[2][4], b[4][2];
        #pragma unroll
        for (int mi = 0; mi < 2; mi++) {
          int rb = wm*32 + mi*16;
          a[mi][0] = __float_as_uint(As[(rb+g8  )*AS_STR + kb+tg  ]);
          a[mi][1] = __float_as_uint(As[(rb+g8+8)*AS_STR + kb+tg  ]);
          a[mi][2] = __float_as_uint(As[(rb+g8  )*AS_STR + kb+tg+4]);
          a[mi][3] = __float_as_uint(As[(rb+g8+8)*AS_STR + kb+tg+4]);
        }
        #pragma unroll
        for (int ni = 0; ni < 4; ni++) {
          int nc = wn*32 + ni*8 + g8;
          b[ni][0] = __float_as_uint(Bs[(kb+tg  )*BS_STR + nc]);
          b[ni][1] = __float_as_uint(Bs[(kb+tg+4)*BS_STR + nc]);
        }
        #pragma unroll
        for (int mi = 0; mi < 2; mi++)
          #pragma unroll
          for (int ni = 0; ni < 4; ni++)
            mma8(acc[mi][ni], a[mi], b[ni]);
      }
      __syncthreads();
    }

    // dump accumulators to Es
    #pragma unroll
    for (int mi = 0; mi < 2; mi++) {
      int r0 = wm*32 + mi*16 + g8;
      #pragma unroll
      for (int ni = 0; ni < 4; ni++) {
        int c0 = wn*32 + ni*8 + 2*tg;
        Es[ r0   *ES_STR + c0  ] = acc[mi][ni][0];
        Es[ r0   *ES_STR + c0+1] = acc[mi][ni][1];
        Es[(r0+8)*ES_STR + c0  ] = acc[mi][ni][2];
        Es[(r0+8)*ES_STR + c0+1] = acc[mi][ni][3];
      }
    }
    __syncthreads();

    // epilogue: 64 rows x 32 h-units
    #pragma unroll
    for (int it = 0; it < 8; it++) {
      int item = it*256 + tid;
      int r = item >> 5, u = item & 31;
      int p = plist[r];
      if (p < 0) continue;
      int hu = hbase + u;
      float vi = Es[r*ES_STR + 4*u+0] + Bb[4*u+0];
      float vf = Es[r*ES_STR + 4*u+1] + Bb[4*u+1];
      float vg = Es[r*ES_STR + 4*u+2] + Bb[4*u+2];
      float vo = Es[r*ES_STR + 4*u+3] + Bb[4*u+3];
      if (g_m[p]) {
        size_t pb = (size_t)p*G4 + hu;
        g_pre[pb + 0*HQ] = vi;
        g_pre[pb + 1*HQ] = vf;
        g_pre[pb + 2*HQ] = vg;
        g_pre[pb + 3*HQ] = vo;
      } else {
        int t = p & (TQ-1);
        int len = __ldg(&length[p >> 10]);
        float a = (t < len) ? 1.0f : 0.0f;
        int sf = (p + 1 < BT) ? (int)g_m[p+1] : 0;
        int em = g_emit[p];
        if (!sf && em < 0) continue;
        float c2 = sigf(vi) * tanhf(vg);
        float h2 = sigf(vo) * tanhf(c2);
        float hv = a * h2;
        if (sf) {
          g_H[(size_t)p*HQ + hu] = hv;
          g_C[(size_t)p*HQ + hu] = a * c2;
        }
        if (em >= 0) out[(size_t)em*HQ + hu] = hv;
      }
    }
  }
}

// Level pass L: gates = pre + h_{t-1} @ W_hh^T (tf32 tensor MMA)
__global__ __launch_bounds__(256) void k_level(
    const float* __restrict__ W_hh, const int* __restrict__ length,
    float* __restrict__ out, int L) {
  __shared__ float SM[8448];
  __shared__ int plist[BM];
  float* As = SM;
  float* Bs = SM + 2304;
  float* Es = SM;

  int count = g_lvlcount[L];
  if (count == 0) return;
  int nmt = (count + BM - 1) / BM;
  int hbase = blockIdx.y * 32;
  int tid = threadIdx.x;
  int wid = tid >> 5, lane = tid & 31;
  int wm = wid & 1, wn = wid >> 1;
  int g8 = lane >> 2, tg = lane & 3;

  for (int mt = blockIdx.x; mt < nmt; mt += gridDim.x) {
    __syncthreads();
    if (tid < BM) {
      int idx = mt*BM + tid;
      plist[tid] = (idx < count) ? g_lvllist[(size_t)L*BT + idx] : -1;
    }
    __syncthreads();

    float acc[2][4][4];
    #pragma unroll
    for (int i = 0; i < 2; i++)
      #pragma unroll
      for (int j = 0; j < 4; j++)
        #pragma unroll
        for (int q = 0; q < 4; q++) acc[i][j][q] = 0.0f;

    for (int kc = 0; kc < HQ; kc += BKC) {
      {
        int row = tid >> 2, q = tid & 3;
        int p = plist[row]; if (p < 0) p = 1;
        const float* src = g_H + (size_t)(p-1)*HQ + kc + q*8;
        #pragma unroll
        for (int h = 0; h < 2; h++) {
          float4 v = *((const float4*)(src + h*4));
          float* d = As + row*AS_STR + q*8 + h*4;
          d[0]=tf32r(v.x); d[1]=tf32r(v.y); d[2]=tf32r(v.z); d[3]=tf32r(v.w);
        }
      }
      {
        int c = tid >> 1, half = tid & 1;
        int j = (c & 3)*HQ + hbase + (c >> 2);
        const float* src = W_hh + (size_t)j*HQ + kc + half*16;
        #pragma unroll
        for (int h = 0; h < 4; h++) {
          float4 v = *((const float4*)(src + h*4));
          int kk = half*16 + h*4;
          Bs[(kk+0)*BS_STR + c] = tf32r(v.x);
          Bs[(kk+1)*BS_STR + c] = tf32r(v.y);
          Bs[(kk+2)*BS_STR + c] = tf32r(v.z);
          Bs[(kk+3)*BS_STR + c] = tf32r(v.w);
        }
      }
      __syncthreads();
      #pragma unroll
      for (int k8 = 0; k8 < 4; k8++) {
        int kb = k8*8;
        unsigned a[2][4], b[4][2];
        #pragma unroll
        for (int mi = 0; mi < 2; mi++) {
          int rb = wm*32 + mi*16;
          a[mi][0] = __float_as_uint(As[(rb+g8  )*AS_STR + kb+tg  ]);
          a[mi][1] = __float_as_uint(As[(rb+g8+8)*AS_STR + kb+tg  ]);
          a[mi][2] = __float_as_uint(As[(rb+g8  )*AS_STR + kb+tg+4]);
          a[mi][3] = __float_as_uint(As[(rb+g8+8)*AS_STR + kb+tg+4]);
        }
        #pragma unroll
        for (int ni = 0; ni < 4; ni++) {
          int nc = wn*32 + ni*8 + g8;
          b[ni][0] = __float_as_uint(Bs[(kb+tg  )*BS_STR + nc]);
          b[ni][1] = __float_as_uint(Bs[(kb+tg+4)*BS_STR + nc]);
        }
        #pragma unroll
        for (int mi = 0; mi < 2; mi++)
          #pragma unroll
          for (int ni = 0; ni < 4; ni++)
            mma8(acc[mi][ni], a[mi], b[ni]);
      }
      __syncthreads();
    }

    #pragma unroll
    for (int mi = 0; mi < 2; mi++) {
      int r0 = wm*32 + mi*16 + g8;
      #pragma unroll
      for (int ni = 0; ni < 4; ni++) {
        int c0 = wn*32 + ni*8 + 2*tg;
        Es[ r0   *ES_STR + c0  ] = acc[mi][ni][0];
        Es[ r0   *ES_STR + c0+1] = acc[mi][ni][1];
        Es[(r0+8)*ES_STR + c0  ] = acc[mi][ni][2];
        Es[(r0+8)*ES_STR + c0+1] = acc[mi][ni][3];
      }
    }
    __syncthreads();

    #pragma unroll
    for (int it = 0; it < 8; it++) {
      int item = it*256 + tid;
      int r = item >> 5, u = item & 31;
      int p = plist[r];
      if (p < 0) continue;
      int hu = hbase + u;
      int t = p & (TQ-1);
      int len = __ldg(&length[p >> 10]);
      float a = (t < len) ? 1.0f : 0.0f;
      int sf = (p + 1 < BT) ? (int)g_m[p+1] : 0;
      int em = g_emit[p];
      size_t pb = (size_t)p*G4 + hu;
      float vi = Es[r*ES_STR + 4*u+0] + g_pre[pb + 0*HQ];
      float vf = Es[r*ES_STR + 4*u+1] + g_pre[pb + 1*HQ];
      float vg = Es[r*ES_STR + 4*u+2] + g_pre[pb + 2*HQ];
      float vo = Es[r*ES_STR + 4*u+3] + g_pre[pb + 3*HQ];
      float hin = g_H[(size_t)(p-1)*HQ + hu];
      float cin = g_C[(size_t)(p-1)*HQ + hu];
      float c2 = sigf(vf)*cin + sigf(vi)*tanhf(vg);
      float h2 = sigf(vo)*tanhf(c2);
      float hv = a*h2 + (1.0f - a)*hin;
      float cv = a*c2 + (1.0f - a)*cin;
      if (sf) {
        g_H[(size_t)p*HQ + hu] = hv;
        g_C[(size_t)p*HQ + hu] = cv;
      }
      if (em >= 0) out[(size_t)em*HQ + hu] = a*h2;
    }
  }
}

extern "C" void kernel_launch(void* const* d_in, const int* in_sizes, int n_in,
                              void* d_out, int out_size) {
  const float* x      = (const float*)d_in[0];
  const int*   mask   = (const int*)d_in[1];
  const int*   length = (const int*)d_in[2];
  const float* W_ih   = (const float*)d_in[3];
  const float* W_hh   = (const float*)d_in[4];
  const float* b_ih   = (const float*)d_in[5];
  const float* b_hh   = (const float*)d_in[6];
  float* out = (float*)d_out;

  long long per = (long long)BQ * HQ;
  int K, has_wn;
  if ((long long)out_size % per == 0) { K = (int)((long long)out_size / per); has_wn = 0; }
  else { K = (int)(((long long)out_size - BQ) / per); has_wn = 1; }

  k_init<<<(BT + 255)/256, 256>>>();
  k_row<<<BQ, 32>>>(mask, length, out, K, has_wn);
  k_work<<<(BT + 255)/256, 256>>>();
  k_main<<<dim3(256, 16), 256>>>(x, length, W_ih, b_ih, b_hh, out);
  for (int L = 1; L <= MAXLEV; L++) {
    int gx = (L == 1) ? 192 : (L == 2) ? 32 : 4;
    k_level<<<dim3(gx, 16), 256>>>(W_hh, length, out, L);
  }
}